// round 9
// baseline (speedup 1.0000x reference)
#include <cuda_runtime.h>
#include <math.h>
#include <float.h>

// ---------------------------------------------------------------------------
// PointPWC multi-scale loss — 2D (x-slab, y-bin) sorted exact kNN.
// Round 9: one query per warp, slim event loop, A+B+D / C kernel split.
// ---------------------------------------------------------------------------

#define TB 256
#define FULLM 0xffffffffu
#define XS 64
#define YB 160
#define NBIN2 (XS * YB)
#define XLO (-6.0f)
#define YLO (-6.0f)
#define SW  (12.0f / XS)
#define YW  (12.0f / YB)
#define XSC (XS / 12.0f)
#define YSC (YB / 12.0f)

__device__ float4 g_s1p[30720];
__device__ float4 g_s1w[30720];
__device__ float4 g_s2 [30720];
__device__ float4 g_sw [30720];
__device__ float4 g_cv2[30720];
__device__ float4 g_cvw[30720];
__device__ int    g_binstart[24 * NBIN2];

struct InPtrs { const float* p[12]; };

__device__ __forceinline__ float wsum32(float v) {
#pragma unroll
    for (int o = 16; o; o >>= 1) v += __shfl_xor_sync(FULLM, v, o);
    return v;
}
__device__ __forceinline__ int slabOf(float x) {
    int s = (int)((x - XLO) * XSC);
    return min(XS - 1, max(0, s));
}
__device__ __forceinline__ int ybinOf(float y) {
    int b = (int)((y - YLO) * YSC);
    return min(YB - 1, max(0, b));
}
__device__ __forceinline__ float dxsqSlab(float qx, int sl) {
    float lo = XLO + sl * SW, hi = lo + SW;
    float d = fmaxf(0.0f, fmaxf(lo - qx, qx - hi));
    return d * d;
}

// Warp bitonic sort of (d, p) ascending. 15 stages.
__device__ __forceinline__ void bitonic32(int lane, float& d, int& p) {
#pragma unroll
    for (int k = 2; k <= 32; k <<= 1) {
#pragma unroll
        for (int j = k >> 1; j > 0; j >>= 1) {
            float od = __shfl_xor_sync(FULLM, d, j);
            int   op = __shfl_xor_sync(FULLM, p, j);
            bool lower = ((lane & j) == 0);
            bool up    = ((lane & k) == 0);
            bool less  = (od < d) || (od == d && op < p);
            if (less == (lower == up)) { d = od; p = op; }
        }
    }
}

// Slim event loop: ballot against a STALE gate (conservative superset); the
// sorted insert itself is exact. Returns true if any event fired.
template <int K>
__device__ __forceinline__ bool eventLoop(int lane, float& u, int pp,
                                          float& ld, int& lp, float g) {
    bool had = false;
    for (;;) {
        unsigned bal = __ballot_sync(FULLM, u < g);
        if (!bal) break;
        had = true;
        int src = __ffs(bal) - 1;
        float bt = __shfl_sync(FULLM, u, src);
        int   bp = __shfl_sync(FULLM, pp, src);
        if (lane == src) u = FLT_MAX;
        bool ins = (lane < K) && (bt < ld);
        unsigned im = __ballot_sync(FULLM, ins);
        float pd = __shfl_up_sync(FULLM, ld, 1);
        int   pi = __shfl_up_sync(FULLM, lp, 1);
        bool pins = (lane > 0) && ((im >> (lane - 1)) & 1u);
        if (ins) { ld = pins ? pd : bt; lp = pins ? pi : bp; }
    }
    return had;
}

// ---------------------------------------------------------------------------
// y-window scan of one slab for ONE query, excluding flat [wlo, whi).
// ---------------------------------------------------------------------------
template <int K>
__device__ void scanSlab(const float4* __restrict__ R, const int* __restrict__ bs,
                         int N, int lane, int sl, float dx,
                         float4 q, int wlo, int whi,
                         float& ld, int& lp, float& g) {
    int sbeg = __ldg(&bs[sl * YB]);
    int send = (sl == XS - 1) ? N : __ldg(&bs[(sl + 1) * YB]);
    if (sbeg >= send) return;

    const float a0 = -2.f * q.x, b0 = -2.f * q.y, c0 = -2.f * q.z;

    int yb = ybinOf(q.y);
    int st = __ldg(&bs[sl * YB + yb]);
    st = min(max(st, sbeg), send);
    int l = st - 1, r = st;
    float upperL = YLO + yb * YW;
    float lowerR = YLO + yb * YW;

    for (;;) {
        float e = q.y - upperL;
        bool ldone = (l < sbeg) || ((e >= 0.f) & (fmaf(e, e, dx) >= g));
        float f = lowerR - q.y;
        bool rdone = (r >= send) || ((f >= 0.f) & (fmaf(f, f, dx) >= g));
        if (ldone && rdone) break;

        bool goLeft = !ldone && (rdone || (q.y - upperL) <= (lowerR - q.y));
        int pbase;
        if (goLeft) { pbase = l - 31; l -= 32; }
        else        { pbase = r;      r += 32; }

        int pos = pbase + lane;
        bool inRange = (pos >= sbeg) & (pos < send);
        bool valid = inRange & ((pos < wlo) | (pos >= whi));
        float4 ra = __ldg(&R[inRange ? pos : sbeg]);
        if (goLeft) {
            float y0 = __shfl_sync(FULLM, ra.y, 0);
            upperL = YLO + (ybinOf(y0) + 1) * YW;
        } else {
            float y31 = __shfl_sync(FULLM, ra.y, 31);
            lowerR = YLO + ybinOf(y31) * YW;
        }
        float u = fmaf(a0, ra.x, fmaf(b0, ra.y, fmaf(c0, ra.z, ra.w + q.w)));
        if (!valid) u = FLT_MAX;

        if (eventLoop<K>(lane, u, pos, ld, lp, g))
            g = __shfl_sync(FULLM, ld, K - 1);
    }
}

// ---------------------------------------------------------------------------
// 2D window kNN for ONE query. Lane r -> r-th nearest (true sqdist, ascending).
// ---------------------------------------------------------------------------
template <int K>
__device__ void windowKNN2D(const float4* __restrict__ R, int N,
                            const int* __restrict__ bs, int lane,
                            float4 q, int flatStart, float& od, int& op) {
    const float a0 = -2.f * q.x, b0 = -2.f * q.y, c0 = -2.f * q.z;

    int c = flatStart - 15;
    if (c < 0) c = 0;
    if (c > N - 32) c = N - 32;
    int pos = c + lane;
    float4 rp = __ldg(&R[pos]);
    float t = fmaf(a0, rp.x, fmaf(b0, rp.y, fmaf(c0, rp.z, rp.w + q.w)));

    float ld; int lp; float g;
    if (K == 1) {
        float m = t; int j = pos;
#pragma unroll
        for (int o = 16; o; o >>= 1) {
            float om = __shfl_xor_sync(FULLM, m, o);
            int   oj = __shfl_xor_sync(FULLM, j, o);
            if (om < m || (om == m && oj < j)) { m = om; j = oj; }
        }
        ld = (lane == 0) ? m : FLT_MAX; lp = j; g = m;
    } else {
        float sd = t; int sp = pos;
        bitonic32(lane, sd, sp);
        ld = (lane < K) ? sd : FLT_MAX; lp = sp;
        g = __shfl_sync(FULLM, sd, K - 1);
    }

    const int wlo = c, whi = c + 32;
    const int sl0 = slabOf(q.x);

    scanSlab<K>(R, bs, N, lane, sl0, 0.0f, q, wlo, whi, ld, lp, g);

    for (int ds = 1; ds < XS; ++ds) {
        bool any = false;
        int sl = sl0 - ds;
        if (sl >= 0) {
            float dx = dxsqSlab(q.x, sl);
            if (dx < g) {
                scanSlab<K>(R, bs, N, lane, sl, dx, q, wlo, whi, ld, lp, g);
                any = true;
            }
        }
        int sr = sl0 + ds;
        if (sr < XS) {
            float dx = dxsqSlab(q.x, sr);
            if (dx < g) {
                scanSlab<K>(R, bs, N, lane, sr, dx, q, wlo, whi, ld, lp, g);
                any = true;
            }
        }
        if (!any) break;
    }
    od = ld; op = lp;
}

// ---------------------------------------------------------------------------
// One-kernel 2D counting sort: 24 blocks, one (scale,batch,array) group each.
// ---------------------------------------------------------------------------
__global__ void __launch_bounds__(1024)
kSortAll(InPtrs in, float* __restrict__ out) {
    __shared__ int hist[NBIN2];
    __shared__ int wsums[32];
    const int NS[4]   = {8192, 4096, 2048, 1024};
    const int SOFF[4] = {0, 16384, 24576, 28672};
    int g = blockIdx.x;
    if (g == 0 && threadIdx.x == 0) out[0] = 0.0f;
    int s = g / 6, rem = g % 6, b = rem / 3, arr = rem % 3;
    const int N = NS[s];
    const float* P1 = in.p[s]     + (size_t)b * 3 * N;
    const float* P2 = in.p[4 + s] + (size_t)b * 3 * N;
    const float* F  = in.p[8 + s] + (size_t)b * 3 * N;
    const int t = threadIdx.x;
    const int lane = t & 31, w = t >> 5;
    const int PERT = NBIN2 / 1024;

#pragma unroll
    for (int j = 0; j < PERT; ++j) hist[t * PERT + j] = 0;
    __syncthreads();

    for (int i = t; i < N; i += 1024) {
        float x, y;
        if      (arr == 0) { x = P1[i]; y = P1[i + N]; }
        else if (arr == 1) { x = P2[i]; y = P2[i + N]; }
        else               { x = P1[i] + F[i]; y = P1[i + N] + F[i + N]; }
        atomicAdd(&hist[slabOf(x) * YB + ybinOf(y)], 1);
    }
    __syncthreads();

    int loc[PERT]; int sum = 0;
#pragma unroll
    for (int j = 0; j < PERT; ++j) { loc[j] = hist[t * PERT + j]; sum += loc[j]; }
    int v = sum;
#pragma unroll
    for (int o = 1; o < 32; o <<= 1) {
        int u = __shfl_up_sync(FULLM, v, o);
        if (lane >= o) v += u;
    }
    if (lane == 31) wsums[w] = v;
    __syncthreads();
    if (t < 32) {
        int wv = wsums[t];
#pragma unroll
        for (int o = 1; o < 32; o <<= 1) {
            int u = __shfl_up_sync(FULLM, wv, o);
            if (t >= o) wv += u;
        }
        wsums[t] = wv;
    }
    __syncthreads();
    int run = v - sum + (w > 0 ? wsums[w - 1] : 0);
#pragma unroll
    for (int j = 0; j < PERT; ++j) {
        int ccc = loc[j];
        g_binstart[g * NBIN2 + t * PERT + j] = run;
        hist[t * PERT + j] = run;
        run += ccc;
    }
    __syncthreads();

    int gbase = SOFF[s] + b * N;
    for (int i = t; i < N; i += 1024) {
        float x, y, z;
        if (arr == 0)      { x = P1[i]; y = P1[i + N]; z = P1[i + 2 * N]; }
        else if (arr == 1) { x = P2[i]; y = P2[i + N]; z = P2[i + 2 * N]; }
        else { x = P1[i] + F[i]; y = P1[i + N] + F[i + N]; z = P1[i + 2 * N] + F[i + 2 * N]; }
        int bin = slabOf(x) * YB + ybinOf(y);
        int pos = atomicAdd(&hist[bin], 1);
        int dst = gbase + pos;
        if (arr == 0) {
            g_s1p[dst] = make_float4(x, y, z, fmaf(x, x, fmaf(y, y, z * z)));
            float wx = x + F[i], wy = y + F[i + N], wz = z + F[i + 2 * N];
            g_s1w[dst] = make_float4(wx, wy, wz, fmaf(wx, wx, fmaf(wy, wy, wz * wz)));
        } else if (arr == 1) {
            g_s2[dst] = make_float4(x, y, z, fmaf(x, x, fmaf(y, y, z * z)));
        } else {
            g_sw[dst] = make_float4(x, y, z, fmaf(x, x, fmaf(y, y, z * z)));
        }
    }
}

// ---------------------------------------------------------------------------
// kABD: type 0 = A (cv2), 1 = B (cvw + smooth), 2 = D (chamfer dist2).
// One query per warp, 8 queries per block.
// ---------------------------------------------------------------------------
__global__ void __launch_bounds__(TB)
kABD(float* __restrict__ out) {
    const int   NS[4]   = {8192, 4096, 2048, 1024};
    const int   SOFF[4] = {0, 16384, 24576, 28672};
    const float AB[4]   = {0.01f, 0.02f, 0.04f, 0.08f};
    int bx = blockIdx.x;
    int s, rel;
    if      (bx < 6144)  { s = 0; rel = bx; }
    else if (bx < 9216)  { s = 1; rel = bx - 6144; }
    else if (bx < 10752) { s = 2; rel = bx - 9216; }
    else                 { s = 3; rel = bx - 10752; }
    const int N = NS[s];
    const int perType = N >> 2;      // (2N)/8 queries per block
    int type = rel / perType;
    int blk = rel - type * perType;

    int lane = threadIdx.x & 31, w = threadIdx.x >> 5;
    int qg = blk * 8 + w;
    int b = (qg >= N);
    int n0 = qg - (b ? N : 0);
    int base = SOFF[s] + (b ? N : 0);
    int grp = (s * 2 + b) * 3;

    __shared__ float acc;
    if (threadIdx.x == 0) acc = 0.0f;
    __syncthreads();
    float contrib = 0.0f;

    if (type == 0) {
        const float4* P = g_s2 + base;
        const int* bs = g_binstart + (grp + 1) * NBIN2;
        float4 q = P[n0];
        float d; int p;
        windowKNN2D<10>(P, N, bs, lane, q, n0, d, p);
        float sx = 0.f, sy = 0.f, sz = 0.f;
        if (lane < 10) { float4 nb = __ldg(&P[p]); sx = nb.x; sy = nb.y; sz = nb.z; }
        sx = wsum32(sx); sy = wsum32(sy); sz = wsum32(sz);
        if (lane == 0) {
            const float inv9 = 1.0f / 9.0f;
            g_cv2[base + n0] = make_float4((sx - 10.0f * q.x) * inv9,
                                           (sy - 10.0f * q.y) * inv9,
                                           (sz - 10.0f * q.z) * inv9, 0.0f);
        }
    } else if (type == 1) {
        const float4* P = g_s1p + base;
        const float4* W = g_s1w + base;
        const int* bs = g_binstart + (grp + 0) * NBIN2;
        float4 q = P[n0];
        float d; int p;
        windowKNN2D<10>(P, N, bs, lane, q, n0, d, p);
        float4 qW = __ldg(&W[n0]);
        float flqx = qW.x - q.x, flqy = qW.y - q.y, flqz = qW.z - q.z;
        float sx = 0.f, sy = 0.f, sz = 0.f, sm = 0.f;
        if (lane < 10) {
            float4 nw = __ldg(&W[p]);
            sx = nw.x; sy = nw.y; sz = nw.z;
            if (lane < 9) {
                float4 np = __ldg(&P[p]);
                float fx = (nw.x - np.x) - flqx;
                float fy = (nw.y - np.y) - flqy;
                float fz = (nw.z - np.z) - flqz;
                sm = sqrtf(fmaf(fx, fx, fmaf(fy, fy, fz * fz)));
            }
        }
        sx = wsum32(sx); sy = wsum32(sy); sz = wsum32(sz); sm = wsum32(sm);
        if (lane == 0) {
            const float inv9 = 1.0f / 9.0f;
            g_cvw[base + n0] = make_float4((sx - 10.0f * qW.x) * inv9,
                                           (sy - 10.0f * qW.y) * inv9,
                                           (sz - 10.0f * qW.z) * inv9, 0.0f);
            contrib = AB[s] * sm * 0.125f;
        }
    } else {
        const float4* R = g_sw + base;
        const float4* Q = g_s2 + base;
        const int* bs = g_binstart + (grp + 2) * NBIN2;
        float4 q = Q[n0];
        int st = __ldg(&bs[slabOf(q.x) * YB + ybinOf(q.y)]);
        float d; int p;
        windowKNN2D<1>(R, N, bs, lane, q, st, d, p);
        float m0 = __shfl_sync(FULLM, d, 0);
        if (lane == 0) contrib = AB[s] * m0;
    }

    if (lane == 0 && contrib != 0.0f) atomicAdd(&acc, contrib);
    __syncthreads();
    if (threadIdx.x == 0 && acc != 0.0f) atomicAdd(out, acc);
}

// ---------------------------------------------------------------------------
// kC: warp->p2 kNN5 -> chamfer dist1 + curvature. One query per warp.
// ---------------------------------------------------------------------------
__global__ void __launch_bounds__(TB)
kC(float* __restrict__ out) {
    const int   NS[4]   = {8192, 4096, 2048, 1024};
    const int   SOFF[4] = {0, 16384, 24576, 28672};
    const float AB[4]   = {0.01f, 0.02f, 0.04f, 0.08f};
    int bx = blockIdx.x;
    int s, blk;
    if      (bx < 2048) { s = 0; blk = bx; }
    else if (bx < 3072) { s = 1; blk = bx - 2048; }
    else if (bx < 3584) { s = 2; blk = bx - 3072; }
    else                { s = 3; blk = bx - 3584; }
    const int N = NS[s];
    const float w_ch = AB[s], w_cv = 0.3f * AB[s];

    int lane = threadIdx.x & 31, w = threadIdx.x >> 5;
    int qg = blk * 8 + w;
    int b = (qg >= N);
    int n0 = qg - (b ? N : 0);
    int base = SOFF[s] + (b ? N : 0);
    int grp = (s * 2 + b) * 3;

    const float4* R = g_s2 + base;
    const float4* Wq = g_s1w + base;
    const int* bs = g_binstart + (grp + 1) * NBIN2;
    float4 q = Wq[n0];
    int st = __ldg(&bs[slabOf(q.x) * YB + ybinOf(q.y)]);
    float d; int p;
    windowKNN2D<5>(R, N, bs, lane, q, st, d, p);

    float dist1 = __shfl_sync(FULLM, d, 0);
    float wgt = 0.0f;
    float4 cc = make_float4(0.f, 0.f, 0.f, 0.f);
    if (lane < 5) {
        wgt = 1.0f / (d + 1e-8f);
        cc = __ldg(&g_cv2[base + p]);
    }
    float wsum = wsum32(wgt);
    float px = 0.f, py = 0.f, pz = 0.f;
    if (lane < 5) {
        float ww = wgt / wsum;
        px = ww * cc.x; py = ww * cc.y; pz = ww * cc.z;
    }
    float ix = wsum32(px), iy = wsum32(py), iz = wsum32(pz);

    __shared__ float acc;
    if (threadIdx.x == 0) acc = 0.0f;
    __syncthreads();
    if (lane == 0) {
        float4 cw = g_cvw[base + n0];
        float ex = ix - cw.x, ey = iy - cw.y, ez = iz - cw.z;
        float curv = fmaf(ex, ex, fmaf(ey, ey, ez * ez));
        atomicAdd(&acc, w_ch * dist1 + w_cv * curv);
    }
    __syncthreads();
    if (threadIdx.x == 0 && acc != 0.0f) atomicAdd(out, acc);
}

// ---------------------------------------------------------------------------

extern "C" void kernel_launch(void* const* d_in, const int* in_sizes, int n_in,
                              void* d_out, int out_size) {
    float* out = (float*)d_out;
    InPtrs in;
    for (int i = 0; i < 12; ++i) in.p[i] = (const float*)d_in[i];

    kSortAll<<<24, 1024>>>(in, out);
    kABD<<<11520, TB>>>(out);
    kC<<<3840, TB>>>(out);
}

// round 10
// speedup vs baseline: 1.0659x; 1.0659x over previous
#include <cuda_runtime.h>
#include <math.h>
#include <float.h>

// ---------------------------------------------------------------------------
// PointPWC multi-scale loss — 2D (x-slab, y-bin) sorted exact kNN.
// Round 10 = Round 8 structure (2 queries/warp, kAB + kCD) + slim event loop
// (stale-gate ballot; gate refreshed once per chunk when events fired).
// ---------------------------------------------------------------------------

#define TB 256
#define FULLM 0xffffffffu
#define XS 64
#define YB 160
#define NBIN2 (XS * YB)          // 10240
#define XLO (-6.0f)
#define YLO (-6.0f)
#define SW  (12.0f / XS)         // 0.1875
#define YW  (12.0f / YB)         // 0.075
#define XSC (XS / 12.0f)
#define YSC (YB / 12.0f)

__device__ float4 g_s1p[30720];
__device__ float4 g_s1w[30720];
__device__ float4 g_s2 [30720];
__device__ float4 g_sw [30720];
__device__ float4 g_cv2[30720];
__device__ float4 g_cvw[30720];
__device__ int    g_binstart[24 * NBIN2];

struct InPtrs { const float* p[12]; };

__device__ __forceinline__ float wsum32(float v) {
#pragma unroll
    for (int o = 16; o; o >>= 1) v += __shfl_xor_sync(FULLM, v, o);
    return v;
}

__device__ __forceinline__ int slabOf(float x) {
    int s = (int)((x - XLO) * XSC);
    return min(XS - 1, max(0, s));
}
__device__ __forceinline__ int ybinOf(float y) {
    int b = (int)((y - YLO) * YSC);
    return min(YB - 1, max(0, b));
}
__device__ __forceinline__ float dxsqSlab(float qx, int sl) {
    float lo = XLO + sl * SW, hi = lo + SW;
    float d = fmaxf(0.0f, fmaxf(lo - qx, qx - hi));
    return d * d;
}

// Warp bitonic sort of (d, p) ascending. 15 stages.
__device__ __forceinline__ void bitonic32(int lane, float& d, int& p) {
#pragma unroll
    for (int k = 2; k <= 32; k <<= 1) {
#pragma unroll
        for (int j = k >> 1; j > 0; j >>= 1) {
            float od = __shfl_xor_sync(FULLM, d, j);
            int   op = __shfl_xor_sync(FULLM, p, j);
            bool lower = ((lane & j) == 0);
            bool up    = ((lane & k) == 0);
            bool less  = (od < d) || (od == d && op < p);
            if (less == (lower == up)) { d = od; p = op; }
        }
    }
}

// Slim event loop: ballot against a STALE gate (conservative superset — a
// candidate >= true Kth fails every per-lane insert test and lands nowhere;
// termination holds because each event retires its source lane). Returns
// whether any event fired so the caller can refresh the gate once per chunk.
template <int K>
__device__ __forceinline__ bool eventLoop(int lane, float& u, int pp,
                                          float& ld, int& lp, float g) {
    bool had = false;
    for (;;) {
        unsigned bal = __ballot_sync(FULLM, u < g);
        if (!bal) break;
        had = true;
        int src = __ffs(bal) - 1;
        float bt = __shfl_sync(FULLM, u, src);
        int   bp = __shfl_sync(FULLM, pp, src);
        if (lane == src) u = FLT_MAX;
        bool ins = (lane < K) && (bt < ld);
        unsigned im = __ballot_sync(FULLM, ins);
        float pd = __shfl_up_sync(FULLM, ld, 1);
        int   pi = __shfl_up_sync(FULLM, lp, 1);
        bool pins = (lane > 0) && ((im >> (lane - 1)) & 1u);
        if (ins) { ld = pins ? pd : bt; lp = pins ? pi : bp; }
    }
    return had;
}

// ---------------------------------------------------------------------------
// y-window scan of one slab for 2 queries, excluding flat [wlo, whi).
// ---------------------------------------------------------------------------
template <int K>
__device__ void scanSlab(const float4* __restrict__ R, const int* __restrict__ bs,
                         int N, int lane, int sl,
                         float dx0, float dx1,
                         float4 q0, float4 q1, int wlo, int whi,
                         float& ld0, int& lp0, float& g0,
                         float& ld1, int& lp1, float& g1) {
    int sbeg = __ldg(&bs[sl * YB]);
    int send = (sl == XS - 1) ? N : __ldg(&bs[(sl + 1) * YB]);
    if (sbeg >= send) return;

    const float a0 = -2.f * q0.x, b0 = -2.f * q0.y, c0 = -2.f * q0.z;
    const float a1 = -2.f * q1.x, b1 = -2.f * q1.y, c1 = -2.f * q1.z;

    int yb = ybinOf(q0.y);
    int st = __ldg(&bs[sl * YB + yb]);
    st = min(max(st, sbeg), send);
    int l = st - 1, r = st;
    float upperL = YLO + yb * YW;
    float lowerR = YLO + yb * YW;

    for (;;) {
        bool ldone, rdone;
        {
            float e0 = q0.y - upperL, e1 = q1.y - upperL;
            ldone = (l < sbeg) ||
                    ((e0 >= 0.f) & (fmaf(e0, e0, dx0) >= g0) &
                     (e1 >= 0.f) & (fmaf(e1, e1, dx1) >= g1));
            float f0 = lowerR - q0.y, f1 = lowerR - q1.y;
            rdone = (r >= send) ||
                    ((f0 >= 0.f) & (fmaf(f0, f0, dx0) >= g0) &
                     (f1 >= 0.f) & (fmaf(f1, f1, dx1) >= g1));
        }
        if (ldone && rdone) break;

        bool goLeft = !ldone && (rdone || (q0.y - upperL) <= (lowerR - q0.y));
        int pbase;
        if (goLeft) { pbase = l - 31; l -= 32; }
        else        { pbase = r;      r += 32; }

        int pos = pbase + lane;
        bool inRange = (pos >= sbeg) & (pos < send);
        bool valid = inRange & ((pos < wlo) | (pos >= whi));
        float4 ra = __ldg(&R[inRange ? pos : sbeg]);
        if (goLeft) {
            float y0 = __shfl_sync(FULLM, ra.y, 0);
            upperL = YLO + (ybinOf(y0) + 1) * YW;
        } else {
            float y31 = __shfl_sync(FULLM, ra.y, 31);
            lowerR = YLO + ybinOf(y31) * YW;
        }
        float u0 = fmaf(a0, ra.x, fmaf(b0, ra.y, fmaf(c0, ra.z, ra.w + q0.w)));
        float u1 = fmaf(a1, ra.x, fmaf(b1, ra.y, fmaf(c1, ra.z, ra.w + q1.w)));
        if (!valid) { u0 = FLT_MAX; u1 = FLT_MAX; }

        bool h0 = eventLoop<K>(lane, u0, pos, ld0, lp0, g0);
        bool h1 = eventLoop<K>(lane, u1, pos, ld1, lp1, g1);
        if (h0) g0 = __shfl_sync(FULLM, ld0, K - 1);
        if (h1) g1 = __shfl_sync(FULLM, ld1, K - 1);
    }
}

// ---------------------------------------------------------------------------
// 2D window kNN for 2 (adjacent) queries. Lane r -> r-th nearest, ascending.
// ---------------------------------------------------------------------------
template <int K>
__device__ void windowKNN2D(const float4* __restrict__ R, int N,
                            const int* __restrict__ bs, int lane,
                            float4 q0, float4 q1, int flatStart,
                            float& od0, int& op0, float& od1, int& op1) {
    const float a0 = -2.f * q0.x, b0 = -2.f * q0.y, c0 = -2.f * q0.z;
    const float a1 = -2.f * q1.x, b1 = -2.f * q1.y, c1 = -2.f * q1.z;

    int c = flatStart - 15;
    if (c < 0) c = 0;
    if (c > N - 32) c = N - 32;
    int pos = c + lane;
    float4 rp = __ldg(&R[pos]);
    float t0 = fmaf(a0, rp.x, fmaf(b0, rp.y, fmaf(c0, rp.z, rp.w + q0.w)));
    float t1 = fmaf(a1, rp.x, fmaf(b1, rp.y, fmaf(c1, rp.z, rp.w + q1.w)));

    float ld0, ld1; int lp0, lp1; float g0, g1;
    if (K == 1) {
        float m0 = t0, m1 = t1;
        int j0 = pos, j1 = pos;
#pragma unroll
        for (int o = 16; o; o >>= 1) {
            float om = __shfl_xor_sync(FULLM, m0, o);
            int   oj = __shfl_xor_sync(FULLM, j0, o);
            if (om < m0 || (om == m0 && oj < j0)) { m0 = om; j0 = oj; }
            float pm = __shfl_xor_sync(FULLM, m1, o);
            int   pj = __shfl_xor_sync(FULLM, j1, o);
            if (pm < m1 || (pm == m1 && pj < j1)) { m1 = pm; j1 = pj; }
        }
        ld0 = (lane == 0) ? m0 : FLT_MAX; lp0 = j0; g0 = m0;
        ld1 = (lane == 0) ? m1 : FLT_MAX; lp1 = j1; g1 = m1;
    } else {
        float sd0 = t0; int sp0 = pos;
        bitonic32(lane, sd0, sp0);
        ld0 = (lane < K) ? sd0 : FLT_MAX; lp0 = sp0;
        g0 = __shfl_sync(FULLM, sd0, K - 1);
        float sd1 = t1; int sp1 = pos;
        bitonic32(lane, sd1, sp1);
        ld1 = (lane < K) ? sd1 : FLT_MAX; lp1 = sp1;
        g1 = __shfl_sync(FULLM, sd1, K - 1);
    }

    const int wlo = c, whi = c + 32;
    const int sl0 = slabOf(q0.x);

    scanSlab<K>(R, bs, N, lane, sl0, dxsqSlab(q0.x, sl0), dxsqSlab(q1.x, sl0),
                q0, q1, wlo, whi, ld0, lp0, g0, ld1, lp1, g1);

    for (int ds = 1; ds < XS; ++ds) {
        bool any = false;
        int sl = sl0 - ds;
        if (sl >= 0) {
            float dx0 = dxsqSlab(q0.x, sl), dx1 = dxsqSlab(q1.x, sl);
            if (dx0 < g0 || dx1 < g1) {
                scanSlab<K>(R, bs, N, lane, sl, dx0, dx1, q0, q1, wlo, whi,
                            ld0, lp0, g0, ld1, lp1, g1);
                any = true;
            }
        }
        int sr = sl0 + ds;
        if (sr < XS) {
            float dx0 = dxsqSlab(q0.x, sr), dx1 = dxsqSlab(q1.x, sr);
            if (dx0 < g0 || dx1 < g1) {
                scanSlab<K>(R, bs, N, lane, sr, dx0, dx1, q0, q1, wlo, whi,
                            ld0, lp0, g0, ld1, lp1, g1);
                any = true;
            }
        }
        if (!any) break;
    }
    od0 = ld0; op0 = lp0; od1 = ld1; op1 = lp1;
}

// ---------------------------------------------------------------------------
// One-kernel 2D counting sort: 24 blocks, one (scale,batch,array) group each.
// ---------------------------------------------------------------------------
__global__ void __launch_bounds__(1024)
kSortAll(InPtrs in, float* __restrict__ out) {
    __shared__ int hist[NBIN2];
    __shared__ int wsums[32];
    const int NS[4]   = {8192, 4096, 2048, 1024};
    const int SOFF[4] = {0, 16384, 24576, 28672};
    int g = blockIdx.x;
    if (g == 0 && threadIdx.x == 0) out[0] = 0.0f;
    int s = g / 6, rem = g % 6, b = rem / 3, arr = rem % 3;
    const int N = NS[s];
    const float* P1 = in.p[s]     + (size_t)b * 3 * N;
    const float* P2 = in.p[4 + s] + (size_t)b * 3 * N;
    const float* F  = in.p[8 + s] + (size_t)b * 3 * N;
    const int t = threadIdx.x;
    const int lane = t & 31, w = t >> 5;
    const int PERT = NBIN2 / 1024;   // 10

#pragma unroll
    for (int j = 0; j < PERT; ++j) hist[t * PERT + j] = 0;
    __syncthreads();

    for (int i = t; i < N; i += 1024) {
        float x, y;
        if      (arr == 0) { x = P1[i]; y = P1[i + N]; }
        else if (arr == 1) { x = P2[i]; y = P2[i + N]; }
        else               { x = P1[i] + F[i]; y = P1[i + N] + F[i + N]; }
        atomicAdd(&hist[slabOf(x) * YB + ybinOf(y)], 1);
    }
    __syncthreads();

    int loc[PERT]; int sum = 0;
#pragma unroll
    for (int j = 0; j < PERT; ++j) { loc[j] = hist[t * PERT + j]; sum += loc[j]; }
    int v = sum;
#pragma unroll
    for (int o = 1; o < 32; o <<= 1) {
        int u = __shfl_up_sync(FULLM, v, o);
        if (lane >= o) v += u;
    }
    if (lane == 31) wsums[w] = v;
    __syncthreads();
    if (t < 32) {
        int wv = wsums[t];
#pragma unroll
        for (int o = 1; o < 32; o <<= 1) {
            int u = __shfl_up_sync(FULLM, wv, o);
            if (t >= o) wv += u;
        }
        wsums[t] = wv;
    }
    __syncthreads();
    int run = v - sum + (w > 0 ? wsums[w - 1] : 0);
#pragma unroll
    for (int j = 0; j < PERT; ++j) {
        int ccc = loc[j];
        g_binstart[g * NBIN2 + t * PERT + j] = run;
        hist[t * PERT + j] = run;
        run += ccc;
    }
    __syncthreads();

    int gbase = SOFF[s] + b * N;
    for (int i = t; i < N; i += 1024) {
        float x, y, z;
        if (arr == 0)      { x = P1[i]; y = P1[i + N]; z = P1[i + 2 * N]; }
        else if (arr == 1) { x = P2[i]; y = P2[i + N]; z = P2[i + 2 * N]; }
        else { x = P1[i] + F[i]; y = P1[i + N] + F[i + N]; z = P1[i + 2 * N] + F[i + 2 * N]; }
        int bin = slabOf(x) * YB + ybinOf(y);
        int pos = atomicAdd(&hist[bin], 1);
        int dst = gbase + pos;
        if (arr == 0) {
            g_s1p[dst] = make_float4(x, y, z, fmaf(x, x, fmaf(y, y, z * z)));
            float wx = x + F[i], wy = y + F[i + N], wz = z + F[i + 2 * N];
            g_s1w[dst] = make_float4(wx, wy, wz, fmaf(wx, wx, fmaf(wy, wy, wz * wz)));
        } else if (arr == 1) {
            g_s2[dst] = make_float4(x, y, z, fmaf(x, x, fmaf(y, y, z * z)));
        } else {
            g_sw[dst] = make_float4(x, y, z, fmaf(x, x, fmaf(y, y, z * z)));
        }
    }
}

// ---------------------------------------------------------------------------
// kAB: type 0 = A (cv2 from p2 self-kNN 10), type 1 = B (cvw + smooth).
// ---------------------------------------------------------------------------
__global__ void __launch_bounds__(TB)
kAB(float* __restrict__ out) {
    const int   NS[4]   = {8192, 4096, 2048, 1024};
    const int   SOFF[4] = {0, 16384, 24576, 28672};
    const float AB[4]   = {0.01f, 0.02f, 0.04f, 0.08f};
    int bx = blockIdx.x;
    int s, rel;
    if      (bx < 2048) { s = 0; rel = bx; }
    else if (bx < 3072) { s = 1; rel = bx - 2048; }
    else if (bx < 3584) { s = 2; rel = bx - 3072; }
    else                { s = 3; rel = bx - 3584; }
    const int N = NS[s];
    const int perType = N >> 3;
    int type = rel / perType;
    int blk = rel - type * perType;

    int lane = threadIdx.x & 31, w = threadIdx.x >> 5;
    int qg = blk * 16 + w * 2;
    int b = (qg >= N);
    int n0 = qg - (b ? N : 0);
    int base = SOFF[s] + (b ? N : 0);
    int grp = (s * 2 + b) * 3;

    __shared__ float acc;
    if (threadIdx.x == 0) acc = 0.0f;
    __syncthreads();
    float contrib = 0.0f;

    if (type == 0) {
        const float4* P = g_s2 + base;
        const int* bs = g_binstart + (grp + 1) * NBIN2;
        float4 q0 = P[n0], q1 = P[n0 + 1];
        float d0, d1; int p0, p1v;
        windowKNN2D<10>(P, N, bs, lane, q0, q1, n0, d0, p0, d1, p1v);
#pragma unroll
        for (int qq = 0; qq < 2; ++qq) {
            int pp = qq ? p1v : p0;
            float sx = 0.f, sy = 0.f, sz = 0.f;
            if (lane < 10) { float4 nb = __ldg(&P[pp]); sx = nb.x; sy = nb.y; sz = nb.z; }
            sx = wsum32(sx); sy = wsum32(sy); sz = wsum32(sz);
            if (lane == 0) {
                float4 q = qq ? q1 : q0;
                const float inv9 = 1.0f / 9.0f;
                g_cv2[base + n0 + qq] = make_float4((sx - 10.0f * q.x) * inv9,
                                                    (sy - 10.0f * q.y) * inv9,
                                                    (sz - 10.0f * q.z) * inv9, 0.0f);
            }
        }
    } else {
        const float4* P = g_s1p + base;
        const float4* W = g_s1w + base;
        const int* bs = g_binstart + (grp + 0) * NBIN2;
        float4 q0 = P[n0], q1 = P[n0 + 1];
        float d0, d1; int p0, p1v;
        windowKNN2D<10>(P, N, bs, lane, q0, q1, n0, d0, p0, d1, p1v);
#pragma unroll
        for (int qq = 0; qq < 2; ++qq) {
            int pp = qq ? p1v : p0;
            const int n = n0 + qq;
            float4 qP = qq ? q1 : q0;
            float4 qW = __ldg(&W[n]);
            float flqx = qW.x - qP.x, flqy = qW.y - qP.y, flqz = qW.z - qP.z;
            float sx = 0.f, sy = 0.f, sz = 0.f, sm = 0.f;
            if (lane < 10) {
                float4 nw = __ldg(&W[pp]);
                sx = nw.x; sy = nw.y; sz = nw.z;
                if (lane < 9) {
                    float4 np = __ldg(&P[pp]);
                    float fx = (nw.x - np.x) - flqx;
                    float fy = (nw.y - np.y) - flqy;
                    float fz = (nw.z - np.z) - flqz;
                    sm = sqrtf(fmaf(fx, fx, fmaf(fy, fy, fz * fz)));
                }
            }
            sx = wsum32(sx); sy = wsum32(sy); sz = wsum32(sz); sm = wsum32(sm);
            if (lane == 0) {
                const float inv9 = 1.0f / 9.0f;
                g_cvw[base + n] = make_float4((sx - 10.0f * qW.x) * inv9,
                                              (sy - 10.0f * qW.y) * inv9,
                                              (sz - 10.0f * qW.z) * inv9, 0.0f);
                contrib += AB[s] * sm * 0.125f;
            }
        }
    }

    if (lane == 0 && contrib != 0.0f) atomicAdd(&acc, contrib);
    __syncthreads();
    if (threadIdx.x == 0 && acc != 0.0f) atomicAdd(out, acc);
}

// ---------------------------------------------------------------------------
// kCD: type 0 = C (warp->p2 kNN5: chamfer1 + curvature), type 1 = D (p2->warp NN).
// ---------------------------------------------------------------------------
__global__ void __launch_bounds__(TB)
kCD(float* __restrict__ out) {
    const int   NS[4]   = {8192, 4096, 2048, 1024};
    const int   SOFF[4] = {0, 16384, 24576, 28672};
    const float AB[4]   = {0.01f, 0.02f, 0.04f, 0.08f};
    int bx = blockIdx.x;
    int s, rel;
    if      (bx < 2048) { s = 0; rel = bx; }
    else if (bx < 3072) { s = 1; rel = bx - 2048; }
    else if (bx < 3584) { s = 2; rel = bx - 3072; }
    else                { s = 3; rel = bx - 3584; }
    const int N = NS[s];
    const int perType = N >> 3;
    int type = rel / perType;
    int blk = rel - type * perType;

    int lane = threadIdx.x & 31, w = threadIdx.x >> 5;
    int qg = blk * 16 + w * 2;
    int b = (qg >= N);
    int n0 = qg - (b ? N : 0);
    int base = SOFF[s] + (b ? N : 0);
    int grp = (s * 2 + b) * 3;

    __shared__ float acc;
    if (threadIdx.x == 0) acc = 0.0f;
    __syncthreads();
    float contrib = 0.0f;

    if (type == 0) {
        const float4* R = g_s2 + base;
        const float4* Wq = g_s1w + base;
        const int* bs = g_binstart + (grp + 1) * NBIN2;
        float4 q0 = Wq[n0], q1 = Wq[n0 + 1];
        int st = __ldg(&bs[slabOf(q0.x) * YB + ybinOf(q0.y)]);
        float d0, d1; int p0, p1v;
        windowKNN2D<5>(R, N, bs, lane, q0, q1, st, d0, p0, d1, p1v);

        const float w_ch = AB[s], w_cv = 0.3f * AB[s];
#pragma unroll
        for (int qq = 0; qq < 2; ++qq) {
            float dd = qq ? d1 : d0;
            int pp = qq ? p1v : p0;
            float dist1 = __shfl_sync(FULLM, dd, 0);
            float wgt = 0.0f;
            float4 cc = make_float4(0.f, 0.f, 0.f, 0.f);
            if (lane < 5) {
                wgt = 1.0f / (dd + 1e-8f);
                cc = __ldg(&g_cv2[base + pp]);
            }
            float wsum = wsum32(wgt);
            float px = 0.f, py = 0.f, pz = 0.f;
            if (lane < 5) {
                float ww = wgt / wsum;
                px = ww * cc.x; py = ww * cc.y; pz = ww * cc.z;
            }
            float ix = wsum32(px), iy = wsum32(py), iz = wsum32(pz);
            if (lane == 0) {
                float4 cw = g_cvw[base + n0 + qq];
                float ex = ix - cw.x, ey = iy - cw.y, ez = iz - cw.z;
                float curv = fmaf(ex, ex, fmaf(ey, ey, ez * ez));
                contrib += w_ch * dist1 + w_cv * curv;
            }
        }
    } else {
        const float4* R = g_sw + base;
        const float4* Q = g_s2 + base;
        const int* bs = g_binstart + (grp + 2) * NBIN2;
        float4 q0 = Q[n0], q1 = Q[n0 + 1];
        int st = __ldg(&bs[slabOf(q0.x) * YB + ybinOf(q0.y)]);
        float d0, d1; int p0, p1v;
        windowKNN2D<1>(R, N, bs, lane, q0, q1, st, d0, p0, d1, p1v);
        float m0 = __shfl_sync(FULLM, d0, 0);
        float m1 = __shfl_sync(FULLM, d1, 0);
        if (lane == 0) contrib = AB[s] * (m0 + m1);
    }

    if (lane == 0 && contrib != 0.0f) atomicAdd(&acc, contrib);
    __syncthreads();
    if (threadIdx.x == 0 && acc != 0.0f) atomicAdd(out, acc);
}

// ---------------------------------------------------------------------------

extern "C" void kernel_launch(void* const* d_in, const int* in_sizes, int n_in,
                              void* d_out, int out_size) {
    float* out = (float*)d_out;
    InPtrs in;
    for (int i = 0; i < 12; ++i) in.p[i] = (const float*)d_in[i];

    kSortAll<<<24, 1024>>>(in, out);
    kAB<<<3840, TB>>>(out);
    kCD<<<3840, TB>>>(out);
}